// round 9
// baseline (speedup 1.0000x reference)
#include <cuda_runtime.h>
#include <cuda_fp16.h>
#include <cstdint>
#include <cstddef>

// ---------------------------------------------------------------------------
// out = sigmoid(relu(x @ W1 + b1) @ W2 + b2)
// fp16 mma.sync (HMMA) GEMMs, fp32 accum.
// Tiles loaded via cp.async.bulk (1D TMA) + mbarrier expect_tx -> near-zero
// SMSP issue cost for loads (vs 8 cyc/LDGSTS). Padded SMEM strides replace
// XOR swizzle (conflict-free ldmatrix).
// (tcgen05 unavailable: harness PTX targets base sm_103, not sm_103a)
// ---------------------------------------------------------------------------

#define DI __device__ __forceinline__

static constexpr int BATCH = 4096;
static constexpr int IN_F  = 2048;
static constexpr int HID_F = 8192;
static constexpr int OUT_F = 2048;

__device__ __align__(16) __half g_x [(size_t)BATCH * IN_F];    // A1 [M,K]
__device__ __align__(16) __half g_w1[(size_t)IN_F  * HID_F];   // B1 [K,N]
__device__ __align__(16) __half g_w2[(size_t)HID_F * OUT_F];   // B2 [K,N]
__device__ __align__(16) __half g_h [(size_t)BATCH * HID_F];   // A2 [M,K]

// ---------------------------------------------------------------------------
DI uint32_t smem_u32(const void* p) {
    uint32_t a;
    asm("{ .reg .u64 t; cvta.to.shared.u64 t, %1; cvt.u32.u64 %0, t; }"
        : "=r"(a) : "l"(p));
    return a;
}

DI void mbar_init(uint32_t a, uint32_t cnt) {
    asm volatile("mbarrier.init.shared.b64 [%0], %1;" :: "r"(a), "r"(cnt) : "memory");
}
DI void mbar_expect_tx(uint32_t a, uint32_t bytes) {
    asm volatile("mbarrier.arrive.expect_tx.shared.b64 _, [%0], %1;"
                 :: "r"(a), "r"(bytes) : "memory");
}
DI void mbar_wait(uint32_t a, uint32_t parity) {
    asm volatile(
        "{\n\t"
        ".reg .pred P;\n\t"
        "WAIT_%=:\n\t"
        "mbarrier.try_wait.parity.acquire.cta.shared::cta.b64 P, [%0], %1, 0x989680;\n\t"
        "@P bra.uni DONE_%=;\n\t"
        "bra.uni WAIT_%=;\n\t"
        "DONE_%=:\n\t"
        "}"
        :: "r"(a), "r"(parity) : "memory");
}

DI void bulk_g2s(uint32_t dst, const void* src, uint32_t bytes, uint32_t mbar) {
    asm volatile(
        "cp.async.bulk.shared::cluster.global.mbarrier::complete_tx::bytes "
        "[%0], [%1], %2, [%3];"
        :: "r"(dst), "l"(src), "r"(bytes), "r"(mbar) : "memory");
}

DI void ldm4(uint32_t* r, uint32_t addr) {
    asm volatile("ldmatrix.sync.aligned.m8n8.x4.shared.b16 {%0,%1,%2,%3}, [%4];"
                 : "=r"(r[0]), "=r"(r[1]), "=r"(r[2]), "=r"(r[3]) : "r"(addr));
}
DI void ldm4t(uint32_t* r, uint32_t addr) {
    asm volatile("ldmatrix.sync.aligned.m8n8.x4.trans.shared.b16 {%0,%1,%2,%3}, [%4];"
                 : "=r"(r[0]), "=r"(r[1]), "=r"(r[2]), "=r"(r[3]) : "r"(addr));
}

DI void mma16816(float* d, const uint32_t* a, uint32_t b0, uint32_t b1) {
    asm volatile(
        "mma.sync.aligned.m16n8k16.row.col.f32.f16.f16.f32 "
        "{%0,%1,%2,%3}, {%4,%5,%6,%7}, {%8,%9}, {%0,%1,%2,%3};"
        : "+f"(d[0]), "+f"(d[1]), "+f"(d[2]), "+f"(d[3])
        : "r"(a[0]), "r"(a[1]), "r"(a[2]), "r"(a[3]), "r"(b0), "r"(b1));
}

// ---------------------------------------------------------------------------
// Prep: pure streaming f32 -> f16 converts
// ---------------------------------------------------------------------------
template <int WHICH>   // 0: x->g_x, 1: W1->g_w1, 2: W2->g_w2
__global__ void convert_kernel(const float* __restrict__ src) {
    __half* dst = WHICH == 0 ? g_x : (WHICH == 1 ? g_w1 : g_w2);
    size_t i = ((size_t)blockIdx.x * 256 + threadIdx.x) * 8;
    float4 v0 = *reinterpret_cast<const float4*>(src + i);
    float4 v1 = *reinterpret_cast<const float4*>(src + i + 4);
    __half2 h[4];
    h[0] = __floats2half2_rn(v0.x, v0.y);
    h[1] = __floats2half2_rn(v0.z, v0.w);
    h[2] = __floats2half2_rn(v1.x, v1.y);
    h[3] = __floats2half2_rn(v1.z, v1.w);
    *reinterpret_cast<uint4*>(&dst[i]) = *reinterpret_cast<const uint4*>(h);
}

// ---------------------------------------------------------------------------
// GEMM: per-CTA 128x128, K-chunk 64, 2-stage bulk-copy pipeline.
// 256 threads = 8 warps as 4(M) x 2(N); warp tile 32x64.
// A tile: 128 rows x 144B stride (128B data + 16B pad)  -> 4-bank shift/row.
// B tile: 64 k-rows x 272B stride (256B data + 16B pad) -> 4-bank shift/row.
// ---------------------------------------------------------------------------
static constexpr int A_STRIDE = 144;
static constexpr int A_TILE   = 128 * A_STRIDE;      // 18432
static constexpr int B_STRIDE = 272;
static constexpr int B_TILE   = 64 * B_STRIDE;       // 17408
static constexpr int STAGE_BYTES = A_TILE + B_TILE;  // 35840
static constexpr int SMEM_DYN    = 1024 + 2 * STAGE_BYTES;
static constexpr uint32_t STAGE_TX = 128 * 128 + 64 * 256;   // 32768 data bytes

template <int EPI>
__global__ __launch_bounds__(256, 2)
void gemm_kernel(const float* __restrict__ bias, float* __restrict__ out_f32) {
    constexpr int KDIM  = EPI ? HID_F : IN_F;
    constexpr int NGLOB = EPI ? OUT_F : HID_F;
    constexpr int NITER = KDIM / 64;
    constexpr size_t LDA  = (size_t)KDIM * 2;    // A row stride bytes
    constexpr size_t LDBN = (size_t)NGLOB * 2;   // B k-row stride bytes
    const __half* A = EPI ? g_h  : g_x;
    const __half* B = EPI ? g_w2 : g_w1;

    extern __shared__ char smem_raw[];
    const uint32_t ctrl  = (smem_u32(smem_raw) + 15) & ~15u;
    const uint32_t sbase = (ctrl + 1023) & ~1023u;
    const uint32_t mb0 = ctrl, mb1 = ctrl + 8;

    const int tid  = threadIdx.x;
    const int lane = tid & 31;
    const int warp = tid >> 5;
    const int wm   = warp & 3;    // 4 warps along M (32 rows each)
    const int wn   = warp >> 2;   // 2 warps along N (64 cols each)
    const int mBase = blockIdx.y * 128;
    const int nBase = blockIdx.x * 128;

    const char* gA = (const char*)(A + (size_t)mBase * KDIM);
    const char* gB = (const char*)(B + nBase);   // [K,N]: column offset only

    if (tid == 0) { mbar_init(mb0, 1); mbar_init(mb1, 1); }
    __syncthreads();

    // producer: one thread issues a whole stage of bulk copies
    auto issue_stage = [&](int it, int s) {
        const uint32_t As = sbase + s * STAGE_BYTES;
        const uint32_t Bs = As + A_TILE;
        const uint32_t mb = s ? mb1 : mb0;
        const char* a = gA + (size_t)it * 128;          // 64 fp16 = 128 bytes
        const char* b = gB + (size_t)it * 64 * LDBN;
        mbar_expect_tx(mb, STAGE_TX);
#pragma unroll 4
        for (int r = 0; r < 128; ++r)
            bulk_g2s(As + r * A_STRIDE, a + (size_t)r * LDA, 128, mb);
#pragma unroll 4
        for (int r = 0; r < 64; ++r)
            bulk_g2s(Bs + r * B_STRIDE, b + (size_t)r * LDBN, 256, mb);
    };

    float acc[2][8][4];
#pragma unroll
    for (int i = 0; i < 2; ++i)
#pragma unroll
        for (int j = 0; j < 8; ++j)
#pragma unroll
            for (int k = 0; k < 4; ++k) acc[i][j][k] = 0.0f;

    // prologue: both stages in flight
    if (tid == 0) {
        issue_stage(0, 0);
        issue_stage(1, 1);
    }

    // A ldmatrix addressing (K-major, padded stride — no swizzle)
    const uint32_t aRowOff = (uint32_t)((wm * 32 + (lane & 15)) * A_STRIDE
                                        + ((lane >> 4) << 4));
    // B ldmatrix.trans addressing ([K,N], padded): thread t -> group q=t/8, r=t%8
    const int q = lane >> 3, r = lane & 7;
    const uint32_t bAddrBase = (uint32_t)(((q & 1) * 8 + r) * B_STRIDE
                                          + (wn * 64 + (q >> 1) * 8) * 2);

    int ph0 = 0, ph1 = 0;
#pragma unroll 1
    for (int it = 0; it < NITER; ++it) {
        const int s = it & 1;
        if (s) { mbar_wait(mb1, ph1); ph1 ^= 1; }
        else   { mbar_wait(mb0, ph0); ph0 ^= 1; }

        const uint32_t As = sbase + s * STAGE_BYTES;
        const uint32_t Bs = As + A_TILE;

#pragma unroll
        for (int ks = 0; ks < 4; ++ks) {
            uint32_t a[2][4], b[4][4];
#pragma unroll
            for (int mt = 0; mt < 2; ++mt)
                ldm4(a[mt], As + aRowOff + (uint32_t)(mt * 16 * A_STRIDE + ks * 32));
            const uint32_t bs = Bs + bAddrBase + (uint32_t)(ks * 16 * B_STRIDE);
#pragma unroll
            for (int nb = 0; nb < 4; ++nb)
                ldm4t(b[nb], bs + nb * 32);
#pragma unroll
            for (int mt = 0; mt < 2; ++mt)
#pragma unroll
                for (int nt = 0; nt < 8; ++nt) {
                    const uint32_t* bb = b[nt >> 1];
                    if (nt & 1) mma16816(acc[mt][nt], a[mt], bb[2], bb[3]);
                    else        mma16816(acc[mt][nt], a[mt], bb[0], bb[1]);
                }
        }

        __syncthreads();   // all warps done reading stage s
        if (it + 2 < NITER && tid == 0)
            issue_stage(it + 2, s);
    }

    // epilogue
#pragma unroll
    for (int mt = 0; mt < 2; ++mt) {
#pragma unroll
        for (int nt = 0; nt < 8; ++nt) {
            const int col = nBase + wn * 64 + nt * 8 + (lane & 3) * 2;
            const float bv0 = __ldg(&bias[col]);
            const float bv1 = __ldg(&bias[col + 1]);
#pragma unroll
            for (int rr = 0; rr < 2; ++rr) {
                const int row = mBase + wm * 32 + mt * 16 + (lane >> 2) + rr * 8;
                float v0 = acc[mt][nt][rr * 2 + 0] + bv0;
                float v1 = acc[mt][nt][rr * 2 + 1] + bv1;
                if (EPI == 0) {
                    __half2 h = __floats2half2_rn(fmaxf(v0, 0.0f), fmaxf(v1, 0.0f));
                    *reinterpret_cast<__half2*>(&g_h[(size_t)row * HID_F + col]) = h;
                } else {
                    float2 o;
                    o.x = 1.0f / (1.0f + __expf(-v0));
                    o.y = 1.0f / (1.0f + __expf(-v1));
                    *reinterpret_cast<float2*>(&out_f32[(size_t)row * OUT_F + col]) = o;
                }
            }
        }
    }
}

// ---------------------------------------------------------------------------
extern "C" void kernel_launch(void* const* d_in, const int* in_sizes, int n_in,
                              void* d_out, int out_size) {
    (void)in_sizes; (void)n_in; (void)out_size;
    const float* x  = (const float*)d_in[0];
    const float* W1 = (const float*)d_in[1];
    const float* b1 = (const float*)d_in[2];
    const float* W2 = (const float*)d_in[3];
    const float* b2 = (const float*)d_in[4];
    float* out = (float*)d_out;

    cudaFuncSetAttribute(gemm_kernel<0>, cudaFuncAttributeMaxDynamicSharedMemorySize, SMEM_DYN);
    cudaFuncSetAttribute(gemm_kernel<1>, cudaFuncAttributeMaxDynamicSharedMemorySize, SMEM_DYN);

    convert_kernel<0><<<(BATCH * IN_F)  / (256 * 8), 256>>>(x);
    convert_kernel<1><<<(IN_F * HID_F)  / (256 * 8), 256>>>(W1);
    convert_kernel<2><<<(HID_F * OUT_F) / (256 * 8), 256>>>(W2);

    // GEMM1: H = relu(x @ W1 + b1) -> fp16 g_h
    gemm_kernel<0><<<dim3(HID_F / 128, BATCH / 128), 256, SMEM_DYN>>>(b1, nullptr);
    // GEMM2: out = sigmoid(H @ W2 + b2) -> f32 d_out
    gemm_kernel<1><<<dim3(OUT_F / 128, BATCH / 128), 256, SMEM_DYN>>>(b2, out);
}

// round 10
// speedup vs baseline: 1.9332x; 1.9332x over previous
#include <cuda_runtime.h>
#include <cuda_fp16.h>
#include <cstdint>
#include <cstddef>

// ---------------------------------------------------------------------------
// out = sigmoid(relu(x @ W1 + b1) @ W2 + b2)
// fp16 mma.sync (HMMA) GEMMs, fp32 accum, 2-stage cp.async pipeline.
// A consumed K-major (ldmatrix), B consumed [K,N]-major via ldmatrix.trans.
// 3 CTAs/SM to overlap load-issue convoys of one CTA with HMMA of another.
// (tcgen05 unavailable: harness PTX targets base sm_103, not sm_103a)
// ---------------------------------------------------------------------------

#define DI __device__ __forceinline__

static constexpr int BATCH = 4096;
static constexpr int IN_F  = 2048;
static constexpr int HID_F = 8192;
static constexpr int OUT_F = 2048;

__device__ __align__(16) __half g_x [(size_t)BATCH * IN_F];    // A1 [M,K]
__device__ __align__(16) __half g_w1[(size_t)IN_F  * HID_F];   // B1 [K,N]
__device__ __align__(16) __half g_w2[(size_t)HID_F * OUT_F];   // B2 [K,N]
__device__ __align__(16) __half g_h [(size_t)BATCH * HID_F];   // A2 [M,K]

// ---------------------------------------------------------------------------
DI uint32_t smem_u32(const void* p) {
    uint32_t a;
    asm("{ .reg .u64 t; cvta.to.shared.u64 t, %1; cvt.u32.u64 %0, t; }"
        : "=r"(a) : "l"(p));
    return a;
}

DI void cp_async16(uint32_t dst, const void* src) {
    asm volatile("cp.async.cg.shared.global [%0], [%1], 16;"
                 :: "r"(dst), "l"(src) : "memory");
}
DI void cp_commit() { asm volatile("cp.async.commit_group;" ::: "memory"); }
template <int N> DI void cp_wait() {
    asm volatile("cp.async.wait_group %0;" :: "n"(N) : "memory");
}

DI void ldm4(uint32_t* r, uint32_t addr) {
    asm volatile("ldmatrix.sync.aligned.m8n8.x4.shared.b16 {%0,%1,%2,%3}, [%4];"
                 : "=r"(r[0]), "=r"(r[1]), "=r"(r[2]), "=r"(r[3]) : "r"(addr));
}

DI void ldm4t(uint32_t* r, uint32_t addr) {
    asm volatile("ldmatrix.sync.aligned.m8n8.x4.trans.shared.b16 {%0,%1,%2,%3}, [%4];"
                 : "=r"(r[0]), "=r"(r[1]), "=r"(r[2]), "=r"(r[3]) : "r"(addr));
}

DI void mma16816(float* d, const uint32_t* a, uint32_t b0, uint32_t b1) {
    asm volatile(
        "mma.sync.aligned.m16n8k16.row.col.f32.f16.f16.f32 "
        "{%0,%1,%2,%3}, {%4,%5,%6,%7}, {%8,%9}, {%0,%1,%2,%3};"
        : "+f"(d[0]), "+f"(d[1]), "+f"(d[2]), "+f"(d[3])
        : "r"(a[0]), "r"(a[1]), "r"(a[2]), "r"(a[3]), "r"(b0), "r"(b1));
}

DI uint32_t sw128(uint32_t o) { return o ^ ((o >> 3) & 0x70); }

// ---------------------------------------------------------------------------
// Prep: pure streaming f32 -> f16 converts (no transposes)
// ---------------------------------------------------------------------------
template <int WHICH>   // 0: x->g_x, 1: W1->g_w1, 2: W2->g_w2
__global__ void convert_kernel(const float* __restrict__ src) {
    __half* dst = WHICH == 0 ? g_x : (WHICH == 1 ? g_w1 : g_w2);
    size_t i = ((size_t)blockIdx.x * 256 + threadIdx.x) * 8;
    float4 v0 = *reinterpret_cast<const float4*>(src + i);
    float4 v1 = *reinterpret_cast<const float4*>(src + i + 4);
    __half2 h[4];
    h[0] = __floats2half2_rn(v0.x, v0.y);
    h[1] = __floats2half2_rn(v0.z, v0.w);
    h[2] = __floats2half2_rn(v1.x, v1.y);
    h[3] = __floats2half2_rn(v1.z, v1.w);
    *reinterpret_cast<uint4*>(&dst[i]) = *reinterpret_cast<const uint4*>(h);
}

// ---------------------------------------------------------------------------
// GEMM: per-CTA 128x128, K-chunk 64, 2-stage cp.async pipeline.
// 256 threads = 8 warps as 4(M) x 2(N); warp tile 32x64.
// A tile: 128 rows x 128B, SW128.  B tile: 64 k-rows x 272B (16B pad).
// ---------------------------------------------------------------------------
static constexpr int A_TILE   = 128 * 128;           // 16384
static constexpr int B_STRIDE = 272;                 // 128 fp16 + 8 pad
static constexpr int B_TILE   = 64 * B_STRIDE;       // 17408
static constexpr int STAGE_BYTES = A_TILE + B_TILE;  // 33792
static constexpr int SMEM_DYN    = 1024 + 2 * STAGE_BYTES;   // 68608

DI void load_tile_a(uint32_t sdst, const char* g, size_t ldb, int tid) {
    // 128 rows x 128B, SW128; 4 chunks/thread @256thr
#pragma unroll
    for (int i = 0; i < 4; ++i) {
        int idx = tid + i * 256;
        int row = idx >> 3;
        int c   = idx & 7;
        uint32_t o = (uint32_t)(row * 128 + c * 16);
        cp_async16(sdst + sw128(o), g + (size_t)row * ldb + c * 16);
    }
}

DI void load_tile_b(uint32_t sdst, const char* g, size_t ldb, int tid) {
    // 64 k-rows x 256B (16 chunks), padded stride 272; 4 chunks/thread @256thr
#pragma unroll
    for (int i = 0; i < 4; ++i) {
        int idx = tid + i * 256;          // 0..1023
        int row = idx >> 4;               // 0..63
        int c   = idx & 15;               // 0..15
        cp_async16(sdst + (uint32_t)(row * B_STRIDE + c * 16),
                   g + (size_t)row * ldb + c * 16);
    }
}

template <int EPI>
__global__ __launch_bounds__(256, 3)
void gemm_kernel(const float* __restrict__ bias, float* __restrict__ out_f32) {
    constexpr int KDIM  = EPI ? HID_F : IN_F;
    constexpr int NGLOB = EPI ? OUT_F : HID_F;
    constexpr int NITER = KDIM / 64;
    constexpr size_t LDA = (size_t)KDIM * 2;    // A row stride bytes
    constexpr size_t LDBN = (size_t)NGLOB * 2;  // B k-row stride bytes
    const __half* A = EPI ? g_h  : g_x;
    const __half* B = EPI ? g_w2 : g_w1;

    extern __shared__ char smem_raw[];
    const uint32_t sbase = (smem_u32(smem_raw) + 1023) & ~1023u;

    const int tid  = threadIdx.x;
    const int lane = tid & 31;
    const int warp = tid >> 5;
    const int wm   = warp & 3;    // 4 warps along M (32 rows each)
    const int wn   = warp >> 2;   // 2 warps along N (64 cols each)
    const int mBase = blockIdx.y * 128;
    const int nBase = blockIdx.x * 128;

    const char* gA = (const char*)(A + (size_t)mBase * KDIM);
    const char* gB = (const char*)(B + nBase);   // [K,N]: column offset only

    float acc[2][8][4];
#pragma unroll
    for (int i = 0; i < 2; ++i)
#pragma unroll
        for (int j = 0; j < 8; ++j)
#pragma unroll
            for (int k = 0; k < 4; ++k) acc[i][j][k] = 0.0f;

    // prologue: stage 0
    load_tile_a(sbase,          gA, LDA, tid);
    load_tile_b(sbase + A_TILE, gB, LDBN, tid);
    cp_commit();

    // A ldmatrix addressing (K-major, SW128): per warp two 16-row tiles
    const uint32_t aRowOff = (uint32_t)((wm * 32 + (lane & 15)) * 128 + ((lane >> 4) << 4));
    // B ldmatrix.trans addressing ([K,N], padded): thread t -> group q=t/8, r=t%8
    const int q = lane >> 3, r = lane & 7;
    const uint32_t bAddrBase = (uint32_t)(((q & 1) * 8 + r) * B_STRIDE
                                          + (wn * 64 + (q >> 1) * 8) * 2);

#pragma unroll 1
    for (int it = 0; it < NITER; ++it) {
        __syncthreads();
        if (it + 1 < NITER) {
            const uint32_t sNext = sbase + ((it + 1) & 1) * STAGE_BYTES;
            load_tile_a(sNext,          gA + (size_t)(it + 1) * 128, LDA, tid);
            load_tile_b(sNext + A_TILE, gB + (size_t)(it + 1) * 64 * LDBN, LDBN, tid);
            cp_commit();
            cp_wait<1>();
        } else {
            cp_wait<0>();
        }
        __syncthreads();

        const uint32_t As = sbase + (it & 1) * STAGE_BYTES;
        const uint32_t Bs = As + A_TILE;

#pragma unroll
        for (int ks = 0; ks < 4; ++ks) {
            uint32_t a[2][4], b[4][4];
#pragma unroll
            for (int mt = 0; mt < 2; ++mt)
                ldm4(a[mt], As + sw128(aRowOff + mt * 16 * 128 + ks * 32));
            const uint32_t bs = Bs + bAddrBase + (uint32_t)(ks * 16 * B_STRIDE);
#pragma unroll
            for (int nb = 0; nb < 4; ++nb)
                ldm4t(b[nb], bs + nb * 32);   // +16 cols = 32 bytes
#pragma unroll
            for (int mt = 0; mt < 2; ++mt)
#pragma unroll
                for (int nt = 0; nt < 8; ++nt) {
                    const uint32_t* bb = b[nt >> 1];
                    if (nt & 1) mma16816(acc[mt][nt], a[mt], bb[2], bb[3]);
                    else        mma16816(acc[mt][nt], a[mt], bb[0], bb[1]);
                }
        }
    }

    // epilogue
#pragma unroll
    for (int mt = 0; mt < 2; ++mt) {
#pragma unroll
        for (int nt = 0; nt < 8; ++nt) {
            const int col = nBase + wn * 64 + nt * 8 + (lane & 3) * 2;
            const float bv0 = __ldg(&bias[col]);
            const float bv1 = __ldg(&bias[col + 1]);
#pragma unroll
            for (int rr = 0; rr < 2; ++rr) {
                const int row = mBase + wm * 32 + mt * 16 + (lane >> 2) + rr * 8;
                float v0 = acc[mt][nt][rr * 2 + 0] + bv0;
                float v1 = acc[mt][nt][rr * 2 + 1] + bv1;
                if (EPI == 0) {
                    __half2 h = __floats2half2_rn(fmaxf(v0, 0.0f), fmaxf(v1, 0.0f));
                    *reinterpret_cast<__half2*>(&g_h[(size_t)row * HID_F + col]) = h;
                } else {
                    float2 o;
                    o.x = 1.0f / (1.0f + __expf(-v0));
                    o.y = 1.0f / (1.0f + __expf(-v1));
                    *reinterpret_cast<float2*>(&out_f32[(size_t)row * OUT_F + col]) = o;
                }
            }
        }
    }
}

// ---------------------------------------------------------------------------
extern "C" void kernel_launch(void* const* d_in, const int* in_sizes, int n_in,
                              void* d_out, int out_size) {
    (void)in_sizes; (void)n_in; (void)out_size;
    const float* x  = (const float*)d_in[0];
    const float* W1 = (const float*)d_in[1];
    const float* b1 = (const float*)d_in[2];
    const float* W2 = (const float*)d_in[3];
    const float* b2 = (const float*)d_in[4];
    float* out = (float*)d_out;

    cudaFuncSetAttribute(gemm_kernel<0>, cudaFuncAttributeMaxDynamicSharedMemorySize, SMEM_DYN);
    cudaFuncSetAttribute(gemm_kernel<1>, cudaFuncAttributeMaxDynamicSharedMemorySize, SMEM_DYN);
    cudaFuncSetAttribute(gemm_kernel<0>, cudaFuncAttributePreferredSharedMemoryCarveout, 100);
    cudaFuncSetAttribute(gemm_kernel<1>, cudaFuncAttributePreferredSharedMemoryCarveout, 100);

    convert_kernel<0><<<(BATCH * IN_F)  / (256 * 8), 256>>>(x);
    convert_kernel<1><<<(IN_F * HID_F)  / (256 * 8), 256>>>(W1);
    convert_kernel<2><<<(HID_F * OUT_F) / (256 * 8), 256>>>(W2);

    // GEMM1: H = relu(x @ W1 + b1) -> fp16 g_h
    gemm_kernel<0><<<dim3(HID_F / 128, BATCH / 128), 256, SMEM_DYN>>>(b1, nullptr);
    // GEMM2: out = sigmoid(H @ W2 + b2) -> f32 d_out
    gemm_kernel<1><<<dim3(OUT_F / 128, BATCH / 128), 256, SMEM_DYN>>>(b2, out);
}

// round 11
// speedup vs baseline: 4.5265x; 2.3414x over previous
#include <cuda_runtime.h>
#include <cuda_fp16.h>
#include <cstdint>
#include <cstddef>

// ---------------------------------------------------------------------------
// out = sigmoid(relu(x @ W1 + b1) @ W2 + b2)
// fp16 mma.sync (HMMA) GEMMs, fp32 accum.
// Scratch tensors stored PRE-TILED in gmem so each GEMM stage tile is one
// contiguous block -> loaded with TWO cp.async.bulk DMA ops per stage
// (near-zero SMSP issue cost; R8's LDGSTS issue was ~45% of tensor issue).
// A tiles: 128x128B, SW128-swizzled in gmem.  B tiles: 64x272B (pad incl.).
// (tcgen05 unavailable: harness PTX targets base sm_103, not sm_103a)
// ---------------------------------------------------------------------------

#define DI __device__ __forceinline__

static constexpr int BATCH = 4096;
static constexpr int IN_F  = 2048;
static constexpr int HID_F = 8192;
static constexpr int OUT_F = 2048;

static constexpr int A_TILE   = 128 * 128;           // bytes (8192 halfs)
static constexpr int B_STRIDE = 272;                 // 256B data + 16B pad
static constexpr int B_TILE   = 64 * B_STRIDE;       // 17408 bytes (8704 halfs)
static constexpr int A_TILE_H = A_TILE / 2;          // halfs
static constexpr int B_TILE_H = B_TILE / 2;          // halfs

// pre-tiled fp16 scratch
// g_x : [BATCH/128][IN_F/64]  A-tiles     g_h : [BATCH/128][HID_F/64] A-tiles
// g_w1: [HID_F/128][IN_F/64]  B-tiles     g_w2: [OUT_F/128][HID_F/64] B-tiles
__device__ __align__(16) __half g_x [(size_t)(BATCH / 128) * (IN_F / 64) * A_TILE_H];
__device__ __align__(16) __half g_w1[(size_t)(HID_F / 128) * (IN_F / 64) * B_TILE_H];
__device__ __align__(16) __half g_w2[(size_t)(OUT_F / 128) * (HID_F / 64) * B_TILE_H];
__device__ __align__(16) __half g_h [(size_t)(BATCH / 128) * (HID_F / 64) * A_TILE_H];

// ---------------------------------------------------------------------------
DI uint32_t smem_u32(const void* p) {
    uint32_t a;
    asm("{ .reg .u64 t; cvta.to.shared.u64 t, %1; cvt.u32.u64 %0, t; }"
        : "=r"(a) : "l"(p));
    return a;
}

DI void mbar_init(uint32_t a, uint32_t cnt) {
    asm volatile("mbarrier.init.shared.b64 [%0], %1;" :: "r"(a), "r"(cnt) : "memory");
}
DI void mbar_expect_tx(uint32_t a, uint32_t bytes) {
    asm volatile("mbarrier.arrive.expect_tx.shared.b64 _, [%0], %1;"
                 :: "r"(a), "r"(bytes) : "memory");
}
DI void mbar_wait(uint32_t a, uint32_t parity) {
    asm volatile(
        "{\n\t"
        ".reg .pred P;\n\t"
        "WAIT_%=:\n\t"
        "mbarrier.try_wait.parity.acquire.cta.shared::cta.b64 P, [%0], %1, 0x989680;\n\t"
        "@P bra.uni DONE_%=;\n\t"
        "bra.uni WAIT_%=;\n\t"
        "DONE_%=:\n\t"
        "}"
        :: "r"(a), "r"(parity) : "memory");
}

DI void bulk_g2s(uint32_t dst, const void* src, uint32_t bytes, uint32_t mbar) {
    asm volatile(
        "cp.async.bulk.shared::cluster.global.mbarrier::complete_tx::bytes "
        "[%0], [%1], %2, [%3];"
        :: "r"(dst), "l"(src), "r"(bytes), "r"(mbar) : "memory");
}

DI void ldm4(uint32_t* r, uint32_t addr) {
    asm volatile("ldmatrix.sync.aligned.m8n8.x4.shared.b16 {%0,%1,%2,%3}, [%4];"
                 : "=r"(r[0]), "=r"(r[1]), "=r"(r[2]), "=r"(r[3]) : "r"(addr));
}
DI void ldm4t(uint32_t* r, uint32_t addr) {
    asm volatile("ldmatrix.sync.aligned.m8n8.x4.trans.shared.b16 {%0,%1,%2,%3}, [%4];"
                 : "=r"(r[0]), "=r"(r[1]), "=r"(r[2]), "=r"(r[3]) : "r"(addr));
}

DI void mma16816(float* d, const uint32_t* a, uint32_t b0, uint32_t b1) {
    asm volatile(
        "mma.sync.aligned.m16n8k16.row.col.f32.f16.f16.f32 "
        "{%0,%1,%2,%3}, {%4,%5,%6,%7}, {%8,%9}, {%0,%1,%2,%3};"
        : "+f"(d[0]), "+f"(d[1]), "+f"(d[2]), "+f"(d[3])
        : "r"(a[0]), "r"(a[1]), "r"(a[2]), "r"(a[3]), "r"(b0), "r"(b1));
}

DI uint32_t sw128(uint32_t o) { return o ^ ((o >> 3) & 0x70); }

// ---------------------------------------------------------------------------
// Prep: f32 -> f16 converts writing the pre-tiled layouts
// ---------------------------------------------------------------------------
// x [M,K] -> A-tiles (swizzled). One 8-float chunk per thread.
__global__ void convert_x_kernel(const float* __restrict__ x) {
    const int id = blockIdx.x * 256 + threadIdx.x;          // over M * K/8
    const int m  = id >> 8;                                 // K/8 = 256
    const int kc = id & 255;                                // 8-elem chunk
    float4 v0 = *reinterpret_cast<const float4*>(x + (size_t)m * IN_F + kc * 8);
    float4 v1 = *reinterpret_cast<const float4*>(x + (size_t)m * IN_F + kc * 8 + 4);
    __half2 h[4];
    h[0] = __floats2half2_rn(v0.x, v0.y);
    h[1] = __floats2half2_rn(v0.z, v0.w);
    h[2] = __floats2half2_rn(v1.x, v1.y);
    h[3] = __floats2half2_rn(v1.z, v1.w);
    const int r = m & 127;
    const uint32_t inTile = (uint32_t)((r * 64 + (kc & 7) * 8) ^ ((r & 7) * 8)); // halfs
    const size_t tile = (size_t)(m >> 7) * (IN_F / 64) + (kc >> 3);
    *reinterpret_cast<uint4*>(&g_x[tile * A_TILE_H + inTile]) =
        *reinterpret_cast<const uint4*>(h);
}

// W [K,N] -> B-tiles (padded rows, no swizzle). One 8-float chunk per thread.
template <int WHICH>   // 1: W1 (K=IN_F,N=HID_F), 2: W2 (K=HID_F,N=OUT_F)
__global__ void convert_w_kernel(const float* __restrict__ W) {
    constexpr int K = WHICH == 1 ? IN_F : HID_F;
    constexpr int N = WHICH == 1 ? HID_F : OUT_F;
    __half* dst = WHICH == 1 ? g_w1 : g_w2;
    const int id = blockIdx.x * 256 + threadIdx.x;          // over K * N/8
    const int k  = id / (N / 8);
    const int nc = id % (N / 8);
    float4 v0 = *reinterpret_cast<const float4*>(W + (size_t)k * N + nc * 8);
    float4 v1 = *reinterpret_cast<const float4*>(W + (size_t)k * N + nc * 8 + 4);
    __half2 h[4];
    h[0] = __floats2half2_rn(v0.x, v0.y);
    h[1] = __floats2half2_rn(v0.z, v0.w);
    h[2] = __floats2half2_rn(v1.x, v1.y);
    h[3] = __floats2half2_rn(v1.z, v1.w);
    const size_t tile = (size_t)(nc >> 4) * (K / 64) + (k >> 6);
    const uint32_t inTile = (uint32_t)((k & 63) * 136 + (nc & 15) * 8);  // halfs
    *reinterpret_cast<uint4*>(&dst[tile * B_TILE_H + inTile]) =
        *reinterpret_cast<const uint4*>(h);
}

// ---------------------------------------------------------------------------
// GEMM: per-CTA 128x128, K-chunk 64, 2-stage bulk-DMA pipeline.
// 256 threads = 8 warps as 4(M) x 2(N); warp tile 32x64 (best measured).
// ---------------------------------------------------------------------------
static constexpr int STAGE_BYTES = A_TILE + B_TILE;   // 33792
static constexpr uint32_t STAGE_TX = (uint32_t)STAGE_BYTES;
static constexpr int SMEM_DYN = 1024 + 2 * STAGE_BYTES;

template <int EPI>
__global__ __launch_bounds__(256, 2)
void gemm_kernel(const float* __restrict__ bias, float* __restrict__ out_f32) {
    constexpr int KDIM  = EPI ? HID_F : IN_F;
    constexpr int NITER = KDIM / 64;
    const __half* A = EPI ? g_h  : g_x;
    const __half* B = EPI ? g_w2 : g_w1;

    extern __shared__ char smem_raw[];
    const uint32_t ctrl  = (smem_u32(smem_raw) + 15) & ~15u;
    const uint32_t sbase = (ctrl + 1023) & ~1023u;
    const uint32_t mb0 = ctrl, mb1 = ctrl + 8;

    const int tid  = threadIdx.x;
    const int lane = tid & 31;
    const int warp = tid >> 5;
    const int wm   = warp & 3;    // 4 warps along M (32 rows each)
    const int wn   = warp >> 2;   // 2 warps along N (64 cols each)
    const int mBase = blockIdx.y * 128;
    const int nBase = blockIdx.x * 128;

    // pre-tiled gmem bases for this CTA
    const char* gA = (const char*)(A + (size_t)blockIdx.y * (KDIM / 64) * A_TILE_H);
    const char* gB = (const char*)(B + (size_t)blockIdx.x * (KDIM / 64) * B_TILE_H);

    if (tid == 0) { mbar_init(mb0, 1); mbar_init(mb1, 1); }
    __syncthreads();

    float acc[2][8][4];
#pragma unroll
    for (int i = 0; i < 2; ++i)
#pragma unroll
        for (int j = 0; j < 8; ++j)
#pragma unroll
            for (int k = 0; k < 4; ++k) acc[i][j][k] = 0.0f;

    // prologue: both stages in flight (2 bulk ops each)
    if (tid == 0) {
        mbar_expect_tx(mb0, STAGE_TX);
        bulk_g2s(sbase,          gA, A_TILE, mb0);
        bulk_g2s(sbase + A_TILE, gB, B_TILE, mb0);
        mbar_expect_tx(mb1, STAGE_TX);
        bulk_g2s(sbase + STAGE_BYTES,          gA + A_TILE, A_TILE, mb1);
        bulk_g2s(sbase + STAGE_BYTES + A_TILE, gB + B_TILE, B_TILE, mb1);
    }

    // smem addressing (same as R8)
    const uint32_t aRowOff = (uint32_t)((wm * 32 + (lane & 15)) * 128 + ((lane >> 4) << 4));
    const int q = lane >> 3, r = lane & 7;
    const uint32_t bAddrBase = (uint32_t)(((q & 1) * 8 + r) * B_STRIDE
                                          + (wn * 64 + (q >> 1) * 8) * 2);

    int ph0 = 0, ph1 = 0;
#pragma unroll 1
    for (int it = 0; it < NITER; ++it) {
        const int s = it & 1;
        if (s) { mbar_wait(mb1, ph1); ph1 ^= 1; }
        else   { mbar_wait(mb0, ph0); ph0 ^= 1; }

        const uint32_t As = sbase + s * STAGE_BYTES;
        const uint32_t Bs = As + A_TILE;

#pragma unroll
        for (int ks = 0; ks < 4; ++ks) {
            uint32_t a[2][4], b[4][4];
#pragma unroll
            for (int mt = 0; mt < 2; ++mt)
                ldm4(a[mt], As + sw128(aRowOff + mt * 16 * 128 + ks * 32));
            const uint32_t bs = Bs + bAddrBase + (uint32_t)(ks * 16 * B_STRIDE);
#pragma unroll
            for (int nb = 0; nb < 4; ++nb)
                ldm4t(b[nb], bs + nb * 32);
#pragma unroll
            for (int mt = 0; mt < 2; ++mt)
#pragma unroll
                for (int nt = 0; nt < 8; ++nt) {
                    const uint32_t* bb = b[nt >> 1];
                    if (nt & 1) mma16816(acc[mt][nt], a[mt], bb[2], bb[3]);
                    else        mma16816(acc[mt][nt], a[mt], bb[0], bb[1]);
                }
        }

        __syncthreads();   // all warps done reading stage s
        if (it + 2 < NITER && tid == 0) {
            const uint32_t mb = s ? mb1 : mb0;
            const uint32_t As2 = sbase + s * STAGE_BYTES;
            mbar_expect_tx(mb, STAGE_TX);
            bulk_g2s(As2,          gA + (size_t)(it + 2) * A_TILE, A_TILE, mb);
            bulk_g2s(As2 + A_TILE, gB + (size_t)(it + 2) * B_TILE, B_TILE, mb);
        }
    }

    // epilogue
#pragma unroll
    for (int mt = 0; mt < 2; ++mt) {
#pragma unroll
        for (int nt = 0; nt < 8; ++nt) {
            const int col = nBase + wn * 64 + nt * 8 + (lane & 3) * 2;
            const float bv0 = __ldg(&bias[col]);
            const float bv1 = __ldg(&bias[col + 1]);
#pragma unroll
            for (int rr = 0; rr < 2; ++rr) {
                const int row = mBase + wm * 32 + mt * 16 + (lane >> 2) + rr * 8;
                float v0 = acc[mt][nt][rr * 2 + 0] + bv0;
                float v1 = acc[mt][nt][rr * 2 + 1] + bv1;
                if (EPI == 0) {
                    // write g_h in tiled+swizzled A-tile layout for GEMM2
                    __half2 h = __floats2half2_rn(fmaxf(v0, 0.0f), fmaxf(v1, 0.0f));
                    const int rr_ = row & 127;
                    const size_t tile = (size_t)(row >> 7) * (HID_F / 64) + (col >> 6);
                    const uint32_t inTile =
                        (uint32_t)(rr_ * 128 + (col & 63) * 2) ^ (uint32_t)((rr_ & 7) << 4);
                    *reinterpret_cast<__half2*>(
                        (char*)g_h + tile * A_TILE + inTile) = h;
                } else {
                    float2 o;
                    o.x = 1.0f / (1.0f + __expf(-v0));
                    o.y = 1.0f / (1.0f + __expf(-v1));
                    *reinterpret_cast<float2*>(&out_f32[(size_t)row * OUT_F + col]) = o;
                }
            }
        }
    }
}

// ---------------------------------------------------------------------------
extern "C" void kernel_launch(void* const* d_in, const int* in_sizes, int n_in,
                              void* d_out, int out_size) {
    (void)in_sizes; (void)n_in; (void)out_size;
    const float* x  = (const float*)d_in[0];
    const float* W1 = (const float*)d_in[1];
    const float* b1 = (const float*)d_in[2];
    const float* W2 = (const float*)d_in[3];
    const float* b2 = (const float*)d_in[4];
    float* out = (float*)d_out;

    cudaFuncSetAttribute(gemm_kernel<0>, cudaFuncAttributeMaxDynamicSharedMemorySize, SMEM_DYN);
    cudaFuncSetAttribute(gemm_kernel<1>, cudaFuncAttributeMaxDynamicSharedMemorySize, SMEM_DYN);

    convert_x_kernel<<<(BATCH * (IN_F / 8)) / 256, 256>>>(x);
    convert_w_kernel<1><<<(IN_F * (HID_F / 8)) / 256, 256>>>(W1);
    convert_w_kernel<2><<<(HID_F * (OUT_F / 8)) / 256, 256>>>(W2);

    // GEMM1: H = relu(x @ W1 + b1) -> fp16 g_h (tiled)
    gemm_kernel<0><<<dim3(HID_F / 128, BATCH / 128), 256, SMEM_DYN>>>(b1, nullptr);
    // GEMM2: out = sigmoid(H @ W2 + b2) -> f32 d_out
    gemm_kernel<1><<<dim3(OUT_F / 128, BATCH / 128), 256, SMEM_DYN>>>(b2, out);
}

// round 12
// speedup vs baseline: 4.5333x; 1.0015x over previous
#include <cuda_runtime.h>
#include <cuda_fp16.h>
#include <cstdint>
#include <cstddef>

// ---------------------------------------------------------------------------
// out = sigmoid(relu(x @ W1 + b1) @ W2 + b2)
// fp16 mma.sync (HMMA) GEMMs, fp32 accum.
// Scratch tensors stored PRE-TILED in gmem; each GEMM stage tile loaded with
// TWO cp.async.bulk DMA ops. 3-stage pipeline -> DMA gets 2 full compute
// iterations of flight time (mbar waits hit the fast path).
// (tcgen05 unavailable: harness PTX targets base sm_103, not sm_103a)
// ---------------------------------------------------------------------------

#define DI __device__ __forceinline__

static constexpr int BATCH = 4096;
static constexpr int IN_F  = 2048;
static constexpr int HID_F = 8192;
static constexpr int OUT_F = 2048;

static constexpr int A_TILE   = 128 * 128;           // bytes (8192 halfs)
static constexpr int B_STRIDE = 272;                 // 256B data + 16B pad
static constexpr int B_TILE   = 64 * B_STRIDE;       // 17408 bytes
static constexpr int A_TILE_H = A_TILE / 2;
static constexpr int B_TILE_H = B_TILE / 2;

// pre-tiled fp16 scratch
__device__ __align__(16) __half g_x [(size_t)(BATCH / 128) * (IN_F / 64) * A_TILE_H];
__device__ __align__(16) __half g_w1[(size_t)(HID_F / 128) * (IN_F / 64) * B_TILE_H];
__device__ __align__(16) __half g_w2[(size_t)(OUT_F / 128) * (HID_F / 64) * B_TILE_H];
__device__ __align__(16) __half g_h [(size_t)(BATCH / 128) * (HID_F / 64) * A_TILE_H];

// ---------------------------------------------------------------------------
DI uint32_t smem_u32(const void* p) {
    uint32_t a;
    asm("{ .reg .u64 t; cvta.to.shared.u64 t, %1; cvt.u32.u64 %0, t; }"
        : "=r"(a) : "l"(p));
    return a;
}

DI void mbar_init(uint32_t a, uint32_t cnt) {
    asm volatile("mbarrier.init.shared.b64 [%0], %1;" :: "r"(a), "r"(cnt) : "memory");
}
DI void mbar_expect_tx(uint32_t a, uint32_t bytes) {
    asm volatile("mbarrier.arrive.expect_tx.shared.b64 _, [%0], %1;"
                 :: "r"(a), "r"(bytes) : "memory");
}
DI void mbar_wait(uint32_t a, uint32_t parity) {
    asm volatile(
        "{\n\t"
        ".reg .pred P;\n\t"
        "WAIT_%=:\n\t"
        "mbarrier.try_wait.parity.acquire.cta.shared::cta.b64 P, [%0], %1, 0x989680;\n\t"
        "@P bra.uni DONE_%=;\n\t"
        "bra.uni WAIT_%=;\n\t"
        "DONE_%=:\n\t"
        "}"
        :: "r"(a), "r"(parity) : "memory");
}

DI void bulk_g2s(uint32_t dst, const void* src, uint32_t bytes, uint32_t mbar) {
    asm volatile(
        "cp.async.bulk.shared::cluster.global.mbarrier::complete_tx::bytes "
        "[%0], [%1], %2, [%3];"
        :: "r"(dst), "l"(src), "r"(bytes), "r"(mbar) : "memory");
}

DI void ldm4(uint32_t* r, uint32_t addr) {
    asm volatile("ldmatrix.sync.aligned.m8n8.x4.shared.b16 {%0,%1,%2,%3}, [%4];"
                 : "=r"(r[0]), "=r"(r[1]), "=r"(r[2]), "=r"(r[3]) : "r"(addr));
}
DI void ldm4t(uint32_t* r, uint32_t addr) {
    asm volatile("ldmatrix.sync.aligned.m8n8.x4.trans.shared.b16 {%0,%1,%2,%3}, [%4];"
                 : "=r"(r[0]), "=r"(r[1]), "=r"(r[2]), "=r"(r[3]) : "r"(addr));
}

DI void mma16816(float* d, const uint32_t* a, uint32_t b0, uint32_t b1) {
    asm volatile(
        "mma.sync.aligned.m16n8k16.row.col.f32.f16.f16.f32 "
        "{%0,%1,%2,%3}, {%4,%5,%6,%7}, {%8,%9}, {%0,%1,%2,%3};"
        : "+f"(d[0]), "+f"(d[1]), "+f"(d[2]), "+f"(d[3])
        : "r"(a[0]), "r"(a[1]), "r"(a[2]), "r"(a[3]), "r"(b0), "r"(b1));
}

DI uint32_t sw128(uint32_t o) { return o ^ ((o >> 3) & 0x70); }

// ---------------------------------------------------------------------------
// Prep: f32 -> f16 converts writing the pre-tiled layouts
// ---------------------------------------------------------------------------
__global__ void convert_x_kernel(const float* __restrict__ x) {
    const int id = blockIdx.x * 256 + threadIdx.x;          // over M * K/8
    const int m  = id >> 8;                                 // K/8 = 256
    const int kc = id & 255;
    float4 v0 = *reinterpret_cast<const float4*>(x + (size_t)m * IN_F + kc * 8);
    float4 v1 = *reinterpret_cast<const float4*>(x + (size_t)m * IN_F + kc * 8 + 4);
    __half2 h[4];
    h[0] = __floats2half2_rn(v0.x, v0.y);
    h[1] = __floats2half2_rn(v0.z, v0.w);
    h[2] = __floats2half2_rn(v1.x, v1.y);
    h[3] = __floats2half2_rn(v1.z, v1.w);
    const int r = m & 127;
    const uint32_t inTile = (uint32_t)((r * 64 + (kc & 7) * 8) ^ ((r & 7) * 8)); // halfs
    const size_t tile = (size_t)(m >> 7) * (IN_F / 64) + (kc >> 3);
    *reinterpret_cast<uint4*>(&g_x[tile * A_TILE_H + inTile]) =
        *reinterpret_cast<const uint4*>(h);
}

template <int WHICH>   // 1: W1 (K=IN_F,N=HID_F), 2: W2 (K=HID_F,N=OUT_F)
__global__ void convert_w_kernel(const float* __restrict__ W) {
    constexpr int K = WHICH == 1 ? IN_F : HID_F;
    constexpr int N = WHICH == 1 ? HID_F : OUT_F;
    __half* dst = WHICH == 1 ? g_w1 : g_w2;
    const int id = blockIdx.x * 256 + threadIdx.x;          // over K * N/8
    const int k  = id / (N / 8);
    const int nc = id % (N / 8);
    float4 v0 = *reinterpret_cast<const float4*>(W + (size_t)k * N + nc * 8);
    float4 v1 = *reinterpret_cast<const float4*>(W + (size_t)k * N + nc * 8 + 4);
    __half2 h[4];
    h[0] = __floats2half2_rn(v0.x, v0.y);
    h[1] = __floats2half2_rn(v0.z, v0.w);
    h[2] = __floats2half2_rn(v1.x, v1.y);
    h[3] = __floats2half2_rn(v1.z, v1.w);
    const size_t tile = (size_t)(nc >> 4) * (K / 64) + (k >> 6);
    const uint32_t inTile = (uint32_t)((k & 63) * 136 + (nc & 15) * 8);  // halfs
    *reinterpret_cast<uint4*>(&dst[tile * B_TILE_H + inTile]) =
        *reinterpret_cast<const uint4*>(h);
}

// ---------------------------------------------------------------------------
// GEMM: per-CTA 128x128, K-chunk 64, 3-stage bulk-DMA pipeline.
// 256 threads = 8 warps as 4(M) x 2(N); warp tile 32x64.
// ---------------------------------------------------------------------------
static constexpr int NSTAGE = 3;
static constexpr int STAGE_BYTES = A_TILE + B_TILE;   // 33792
static constexpr uint32_t STAGE_TX = (uint32_t)STAGE_BYTES;
static constexpr int SMEM_DYN = 1024 + NSTAGE * STAGE_BYTES;   // 102400

template <int EPI>
__global__ __launch_bounds__(256, 2)
void gemm_kernel(const float* __restrict__ bias, float* __restrict__ out_f32) {
    constexpr int KDIM  = EPI ? HID_F : IN_F;
    constexpr int NITER = KDIM / 64;
    const __half* A = EPI ? g_h  : g_x;
    const __half* B = EPI ? g_w2 : g_w1;

    extern __shared__ char smem_raw[];
    const uint32_t ctrl  = (smem_u32(smem_raw) + 15) & ~15u;
    const uint32_t sbase = (ctrl + 1023) & ~1023u;

    const int tid  = threadIdx.x;
    const int lane = tid & 31;
    const int warp = tid >> 5;
    const int wm   = warp & 3;    // 4 warps along M (32 rows each)
    const int wn   = warp >> 2;   // 2 warps along N (64 cols each)
    const int mBase = blockIdx.y * 128;
    const int nBase = blockIdx.x * 128;

    const char* gA = (const char*)(A + (size_t)blockIdx.y * (KDIM / 64) * A_TILE_H);
    const char* gB = (const char*)(B + (size_t)blockIdx.x * (KDIM / 64) * B_TILE_H);

    if (tid == 0) {
        mbar_init(ctrl, 1); mbar_init(ctrl + 8, 1); mbar_init(ctrl + 16, 1);
    }
    __syncthreads();

    float acc[2][8][4];
#pragma unroll
    for (int i = 0; i < 2; ++i)
#pragma unroll
        for (int j = 0; j < 8; ++j)
#pragma unroll
            for (int k = 0; k < 4; ++k) acc[i][j][k] = 0.0f;

    // prologue: all three stages in flight (2 bulk ops each)
    if (tid == 0) {
#pragma unroll
        for (int s = 0; s < NSTAGE; ++s) {
            const uint32_t mb = ctrl + 8 * s;
            const uint32_t As = sbase + s * STAGE_BYTES;
            mbar_expect_tx(mb, STAGE_TX);
            bulk_g2s(As,          gA + (size_t)s * A_TILE, A_TILE, mb);
            bulk_g2s(As + A_TILE, gB + (size_t)s * B_TILE, B_TILE, mb);
        }
    }

    const uint32_t aRowOff = (uint32_t)((wm * 32 + (lane & 15)) * 128 + ((lane >> 4) << 4));
    const int q = lane >> 3, r = lane & 7;
    const uint32_t bAddrBase = (uint32_t)(((q & 1) * 8 + r) * B_STRIDE
                                          + (wn * 64 + (q >> 1) * 8) * 2);

    int ph0 = 0, ph1 = 0, ph2 = 0;
    int s = 0;
#pragma unroll 1
    for (int it = 0; it < NITER; ++it) {
        const uint32_t mb = ctrl + 8 * s;
        if (s == 0)      { mbar_wait(mb, ph0); ph0 ^= 1; }
        else if (s == 1) { mbar_wait(mb, ph1); ph1 ^= 1; }
        else             { mbar_wait(mb, ph2); ph2 ^= 1; }

        const uint32_t As = sbase + s * STAGE_BYTES;
        const uint32_t Bs = As + A_TILE;

#pragma unroll
        for (int ks = 0; ks < 4; ++ks) {
            uint32_t a[2][4], b[4][4];
#pragma unroll
            for (int mt = 0; mt < 2; ++mt)
                ldm4(a[mt], As + sw128(aRowOff + mt * 16 * 128 + ks * 32));
            const uint32_t bs = Bs + bAddrBase + (uint32_t)(ks * 16 * B_STRIDE);
#pragma unroll
            for (int nb = 0; nb < 4; ++nb)
                ldm4t(b[nb], bs + nb * 32);
#pragma unroll
            for (int mt = 0; mt < 2; ++mt)
#pragma unroll
                for (int nt = 0; nt < 8; ++nt) {
                    const uint32_t* bb = b[nt >> 1];
                    if (nt & 1) mma16816(acc[mt][nt], a[mt], bb[2], bb[3]);
                    else        mma16816(acc[mt][nt], a[mt], bb[0], bb[1]);
                }
        }

        __syncthreads();   // all warps done reading stage s
        if (it + NSTAGE < NITER && tid == 0) {
            mbar_expect_tx(mb, STAGE_TX);
            bulk_g2s(As,          gA + (size_t)(it + NSTAGE) * A_TILE, A_TILE, mb);
            bulk_g2s(As + A_TILE, gB + (size_t)(it + NSTAGE) * B_TILE, B_TILE, mb);
        }
        if (++s == NSTAGE) s = 0;
    }

    // epilogue
#pragma unroll
    for (int mt = 0; mt < 2; ++mt) {
#pragma unroll
        for (int nt = 0; nt < 8; ++nt) {
            const int col = nBase + wn * 64 + nt * 8 + (lane & 3) * 2;
            const float bv0 = __ldg(&bias[col]);
            const float bv1 = __ldg(&bias[col + 1]);
#pragma unroll
            for (int rr = 0; rr < 2; ++rr) {
                const int row = mBase + wm * 32 + mt * 16 + (lane >> 2) + rr * 8;
                float v0 = acc[mt][nt][rr * 2 + 0] + bv0;
                float v1 = acc[mt][nt][rr * 2 + 1] + bv1;
                if (EPI == 0) {
                    // write g_h in tiled+swizzled A-tile layout for GEMM2
                    __half2 h = __floats2half2_rn(fmaxf(v0, 0.0f), fmaxf(v1, 0.0f));
                    const int rr_ = row & 127;
                    const size_t tile = (size_t)(row >> 7) * (HID_F / 64) + (col >> 6);
                    const uint32_t inTile =
                        (uint32_t)(rr_ * 128 + (col & 63) * 2) ^ (uint32_t)((rr_ & 7) << 4);
                    *reinterpret_cast<__half2*>(
                        (char*)g_h + tile * A_TILE + inTile) = h;
                } else {
                    float2 o;
                    o.x = 1.0f / (1.0f + __expf(-v0));
                    o.y = 1.0f / (1.0f + __expf(-v1));
                    *reinterpret_cast<float2*>(&out_f32[(size_t)row * OUT_F + col]) = o;
                }
            }
        }
    }
}

// ---------------------------------------------------------------------------
extern "C" void kernel_launch(void* const* d_in, const int* in_sizes, int n_in,
                              void* d_out, int out_size) {
    (void)in_sizes; (void)n_in; (void)out_size;
    const float* x  = (const float*)d_in[0];
    const float* W1 = (const float*)d_in[1];
    const float* b1 = (const float*)d_in[2];
    const float* W2 = (const float*)d_in[3];
    const float* b2 = (const float*)d_in[4];
    float* out = (float*)d_out;

    cudaFuncSetAttribute(gemm_kernel<0>, cudaFuncAttributeMaxDynamicSharedMemorySize, SMEM_DYN);
    cudaFuncSetAttribute(gemm_kernel<1>, cudaFuncAttributeMaxDynamicSharedMemorySize, SMEM_DYN);

    convert_x_kernel<<<(BATCH * (IN_F / 8)) / 256, 256>>>(x);
    convert_w_kernel<1><<<(IN_F * (HID_F / 8)) / 256, 256>>>(W1);
    convert_w_kernel<2><<<(HID_F * (OUT_F / 8)) / 256, 256>>>(W2);

    // GEMM1: H = relu(x @ W1 + b1) -> fp16 g_h (tiled)
    gemm_kernel<0><<<dim3(HID_F / 128, BATCH / 128), 256, SMEM_DYN>>>(b1, nullptr);
    // GEMM2: out = sigmoid(H @ W2 + b2) -> f32 d_out
    gemm_kernel<1><<<dim3(OUT_F / 128, BATCH / 128), 256, SMEM_DYN>>>(b2, out);
}